// round 3
// baseline (speedup 1.0000x reference)
#include <cuda_runtime.h>

#define V 50000
#define NNZ 1600000
#define NB 4
#define FIN 128
#define FOUT 128
#define KCH 5
#define C 512           // FIN * NB, row width of dense X
#define RPB 8           // rows per block in spmm

// ---------------- scratch (static device globals; no allocation allowed) ----
__device__ float g_X[KCH][(size_t)V * C];   // Chebyshev basis vectors
__device__ int   g_count[V];
__device__ int   g_cursor[V];
__device__ int   g_rowptr[V + 1];
__device__ int   g_scol[NNZ];
__device__ float g_sval[NNZ];

// ---------------- CSR build ------------------------------------------------
__global__ void zero_kernel() {
    int i = blockIdx.x * blockDim.x + threadIdx.x;
    if (i < V) { g_count[i] = 0; g_cursor[i] = 0; }
}

__global__ void hist_kernel(const int* __restrict__ rows) {
    int i = blockIdx.x * blockDim.x + threadIdx.x;
    if (i < NNZ) atomicAdd(&g_count[rows[i]], 1);
}

// single-block exclusive scan over g_count -> g_rowptr
__global__ void scan_kernel() {
    __shared__ int warp_sums[32];
    __shared__ int s_carry;
    int tid = threadIdx.x, lane = tid & 31, wid = tid >> 5;
    if (tid == 0) s_carry = 0;
    __syncthreads();
    const int ntiles = (V + 1023) / 1024;
    for (int t = 0; t < ntiles; t++) {
        int carry = s_carry;
        int i = t * 1024 + tid;
        int v = (i < V) ? g_count[i] : 0;
        int x = v;
#pragma unroll
        for (int o = 1; o < 32; o <<= 1) {
            int n = __shfl_up_sync(0xFFFFFFFFu, x, o);
            if (lane >= o) x += n;
        }
        if (lane == 31) warp_sums[wid] = x;
        __syncthreads();
        if (wid == 0) {
            int s = warp_sums[lane];
#pragma unroll
            for (int o = 1; o < 32; o <<= 1) {
                int n = __shfl_up_sync(0xFFFFFFFFu, s, o);
                if (lane >= o) s += n;
            }
            warp_sums[lane] = s;
        }
        __syncthreads();
        int excl = carry + (x - v) + (wid > 0 ? warp_sums[wid - 1] : 0);
        if (i < V) g_rowptr[i] = excl;
        __syncthreads();
        if (tid == 0) s_carry = carry + warp_sums[31];
        __syncthreads();
    }
    if (threadIdx.x == 0) g_rowptr[V] = s_carry;
}

__global__ void scatter_kernel(const int* __restrict__ rows,
                               const int* __restrict__ cols,
                               const float* __restrict__ vals) {
    int i = blockIdx.x * blockDim.x + threadIdx.x;
    if (i < NNZ) {
        int r = rows[i];
        int p = g_rowptr[r] + atomicAdd(&g_cursor[r], 1);
        g_scol[p] = cols[i];
        g_sval[p] = vals[i];
    }
}

// ---------------- transpose: inputs[b][v][f] -> X0[v][f*4+b] ---------------
__global__ void transpose_kernel(const float* __restrict__ inp) {
    int i = blockIdx.x * blockDim.x + threadIdx.x;
    if (i < V * FIN) {
        int v = i >> 7, f = i & 127;
        const size_t VF = (size_t)V * FIN;
        float4 o;
        o.x = inp[(size_t)v * FIN + f];
        o.y = inp[VF + (size_t)v * FIN + f];
        o.z = inp[2 * VF + (size_t)v * FIN + f];
        o.w = inp[3 * VF + (size_t)v * FIN + f];
        *(float4*)&g_X[0][(size_t)v * C + f * 4] = o;
    }
}

// ---------------- SpMM: y = L*x  (or y = 2*L*x - xprev) --------------------
__global__ void spmm_kernel(int kout, int kin, int kprev, int cheb, int chunk) {
    const float* __restrict__ x = g_X[kin];
    const float* __restrict__ xp = g_X[kprev];
    float* __restrict__ y = g_X[kout];
    int col = chunk * 128 + threadIdx.x;
    int r0 = blockIdx.x * RPB;
    int r1 = min(r0 + RPB, V);
    for (int r = r0; r < r1; r++) {
        int s = g_rowptr[r], e = g_rowptr[r + 1];
        float acc = 0.f;
        int i = s;
        for (; i + 4 <= e; i += 4) {
            int   c0 = g_scol[i],     c1 = g_scol[i + 1];
            int   c2 = g_scol[i + 2], c3 = g_scol[i + 3];
            float w0 = g_sval[i],     w1 = g_sval[i + 1];
            float w2 = g_sval[i + 2], w3 = g_sval[i + 3];
            float x0 = __ldg(&x[(size_t)c0 * C + col]);
            float x1 = __ldg(&x[(size_t)c1 * C + col]);
            float x2 = __ldg(&x[(size_t)c2 * C + col]);
            float x3 = __ldg(&x[(size_t)c3 * C + col]);
            acc += w0 * x0 + w1 * x1 + w2 * x2 + w3 * x3;
        }
        for (; i < e; i++)
            acc += g_sval[i] * __ldg(&x[(size_t)g_scol[i] * C + col]);
        size_t oi = (size_t)r * C + col;
        y[oi] = cheb ? 2.f * acc - xp[oi] : acc;
    }
}

// ---------------- GEMM: out[b*V+v][fo] = sum_{k,fin} X[k][v][fin*4+b] * W[(fin*5+k)*128+fo]
// Block tile: 128 rows (= 4 batches x 32 vertices) x 128 cols, K-step 8.
__global__ void __launch_bounds__(256) gemm_kernel(const float* __restrict__ Wt,
                                                   const float* __restrict__ bias,
                                                   float* __restrict__ out) {
    __shared__ float As[8][132];
    __shared__ float Bs[8][132];
    int t = threadIdx.x;
    int tx = t & 15, ty = t >> 4;
    int v0 = blockIdx.x * 32;

    float acc[8][8];
#pragma unroll
    for (int i = 0; i < 8; i++)
#pragma unroll
        for (int j = 0; j < 8; j++) acc[i][j] = 0.f;

    int vl_ld = t >> 3, q_ld = t & 7;           // A-tile loader coords
    int vload = min(v0 + vl_ld, V - 1);
    int jr = t >> 5, c4 = t & 31;               // B-tile loader coords

    for (int kc = 0; kc < KCH; kc++) {
        const float* __restrict__ X = g_X[kc];
        for (int f0 = 0; f0 < FIN; f0 += 8) {
            // global loads: A = 32 vertices x (8 fin x 4 b contiguous floats)
            float4 a = *(const float4*)&X[(size_t)vload * C + (f0 + q_ld) * 4];
            float4 b = *(const float4*)&Wt[(size_t)((f0 + jr) * 5 + kc) * FOUT + c4 * 4];
            __syncthreads();
            As[q_ld][vl_ld]      = a.x;   // b=0
            As[q_ld][32 + vl_ld] = a.y;   // b=1
            As[q_ld][64 + vl_ld] = a.z;   // b=2
            As[q_ld][96 + vl_ld] = a.w;   // b=3
            *(float4*)&Bs[jr][c4 * 4] = b;
            __syncthreads();
#pragma unroll
            for (int p = 0; p < 8; p++) {
                float ar[8], br[8];
                *(float4*)&ar[0] = *(const float4*)&As[p][ty * 8];
                *(float4*)&ar[4] = *(const float4*)&As[p][ty * 8 + 4];
                *(float4*)&br[0] = *(const float4*)&Bs[p][tx * 8];
                *(float4*)&br[4] = *(const float4*)&Bs[p][tx * 8 + 4];
#pragma unroll
                for (int i = 0; i < 8; i++)
#pragma unroll
                    for (int j = 0; j < 8; j++)
                        acc[i][j] += ar[i] * br[j];
            }
        }
    }

    float bs_reg[8];
#pragma unroll
    for (int j = 0; j < 8; j++) bs_reg[j] = bias[tx * 8 + j];

#pragma unroll
    for (int i = 0; i < 8; i++) {
        int rr = ty * 8 + i;
        int bb = rr >> 5, vl = rr & 31;
        int v = v0 + vl;
        if (v < V) {
            size_t base = ((size_t)bb * V + v) * FOUT + tx * 8;
            float4 o0, o1;
            o0.x = acc[i][0] + bs_reg[0]; o0.y = acc[i][1] + bs_reg[1];
            o0.z = acc[i][2] + bs_reg[2]; o0.w = acc[i][3] + bs_reg[3];
            o1.x = acc[i][4] + bs_reg[4]; o1.y = acc[i][5] + bs_reg[5];
            o1.z = acc[i][6] + bs_reg[6]; o1.w = acc[i][7] + bs_reg[7];
            *(float4*)&out[base]     = o0;
            *(float4*)&out[base + 4] = o1;
        }
    }
}

// ---------------- launcher -------------------------------------------------
extern "C" void kernel_launch(void* const* d_in, const int* in_sizes, int n_in,
                              void* d_out, int out_size) {
    const int*   rows   = (const int*)d_in[0];
    const int*   cols   = (const int*)d_in[1];
    const float* vals   = (const float*)d_in[2];
    const float* inputs = (const float*)d_in[3];
    const float* weight = (const float*)d_in[4];
    const float* bias   = (const float*)d_in[5];
    float*       out    = (float*)d_out;

    zero_kernel<<<(V + 255) / 256, 256>>>();
    hist_kernel<<<(NNZ + 255) / 256, 256>>>(rows);
    scan_kernel<<<1, 1024>>>();
    scatter_kernel<<<(NNZ + 255) / 256, 256>>>(rows, cols, vals);
    transpose_kernel<<<(V * FIN + 255) / 256, 256>>>(inputs);

    for (int k = 1; k < KCH; k++) {
        int kprev = (k >= 2) ? k - 2 : 0;
        int cheb  = (k >= 2) ? 1 : 0;
        for (int ch = 0; ch < 4; ch++) {
            spmm_kernel<<<(V + RPB - 1) / RPB, 128>>>(k, k - 1, kprev, cheb, ch);
        }
    }

    gemm_kernel<<<(V + 31) / 32, 256>>>(weight, bias, out);
}

// round 4
// speedup vs baseline: 1.4474x; 1.4474x over previous
#include <cuda_runtime.h>

#define V 50000
#define NNZ 1600000
#define NB 4
#define FIN 128
#define FOUT 128
#define KCH 5
#define C 512           // FIN * NB, row width of dense X
#define SPMM_RPB 2      // rows per block in spmm

// ---------------- scratch (static device globals; no allocation allowed) ----
__device__ float g_X[KCH][(size_t)V * C];   // Chebyshev basis vectors
__device__ int   g_count[V];
__device__ int   g_cursor[V];
__device__ int   g_rowptr[V + 1];
__device__ int   g_scol[NNZ];
__device__ float g_sval[NNZ];

// ---------------- CSR build ------------------------------------------------
__global__ void zero_kernel() {
    int i = blockIdx.x * blockDim.x + threadIdx.x;
    if (i < V) { g_count[i] = 0; g_cursor[i] = 0; }
}

__global__ void hist_kernel(const int* __restrict__ rows) {
    int i = blockIdx.x * blockDim.x + threadIdx.x;
    if (i < NNZ) atomicAdd(&g_count[rows[i]], 1);
}

// single-block exclusive scan over g_count -> g_rowptr
__global__ void scan_kernel() {
    __shared__ int warp_sums[32];
    __shared__ int s_carry;
    int tid = threadIdx.x, lane = tid & 31, wid = tid >> 5;
    if (tid == 0) s_carry = 0;
    __syncthreads();
    const int ntiles = (V + 1023) / 1024;
    for (int t = 0; t < ntiles; t++) {
        int carry = s_carry;
        int i = t * 1024 + tid;
        int v = (i < V) ? g_count[i] : 0;
        int x = v;
#pragma unroll
        for (int o = 1; o < 32; o <<= 1) {
            int n = __shfl_up_sync(0xFFFFFFFFu, x, o);
            if (lane >= o) x += n;
        }
        if (lane == 31) warp_sums[wid] = x;
        __syncthreads();
        if (wid == 0) {
            int s = warp_sums[lane];
#pragma unroll
            for (int o = 1; o < 32; o <<= 1) {
                int n = __shfl_up_sync(0xFFFFFFFFu, s, o);
                if (lane >= o) s += n;
            }
            warp_sums[lane] = s;
        }
        __syncthreads();
        int excl = carry + (x - v) + (wid > 0 ? warp_sums[wid - 1] : 0);
        if (i < V) g_rowptr[i] = excl;
        __syncthreads();
        if (tid == 0) s_carry = carry + warp_sums[31];
        __syncthreads();
    }
    if (threadIdx.x == 0) g_rowptr[V] = s_carry;
}

__global__ void scatter_kernel(const int* __restrict__ rows,
                               const int* __restrict__ cols,
                               const float* __restrict__ vals) {
    int i = blockIdx.x * blockDim.x + threadIdx.x;
    if (i < NNZ) {
        int r = rows[i];
        int p = g_rowptr[r] + atomicAdd(&g_cursor[r], 1);
        g_scol[p] = cols[i];
        g_sval[p] = vals[i];
    }
}

// ---------------- transpose: inputs[b][v][f] -> X0[v][f*4+b] ---------------
__global__ void transpose_kernel(const float* __restrict__ inp) {
    int i = blockIdx.x * blockDim.x + threadIdx.x;
    if (i < V * FIN) {
        int v = i >> 7, f = i & 127;
        const size_t VF = (size_t)V * FIN;
        float4 o;
        o.x = inp[(size_t)v * FIN + f];
        o.y = inp[VF + (size_t)v * FIN + f];
        o.z = inp[2 * VF + (size_t)v * FIN + f];
        o.w = inp[3 * VF + (size_t)v * FIN + f];
        *(float4*)&g_X[0][(size_t)v * C + f * 4] = o;
    }
}

// ---------------- SpMM: y = L*x  (or y = 2*L*x - xprev), full 512-col width
// 128 threads/block, each thread owns one float4 column group (4 cols).
// Per edge: one LDG.128 gather per thread (fully coalesced 512B/warp).
// y stored with .cs (evict-first) and xprev/edges read with .cs so the
// gathered x matrix keeps L2 residency (~102MB of 126MB).
__global__ void __launch_bounds__(128) spmm_kernel(int kout, int kin, int kprev, int cheb) {
    const float4* __restrict__ x  = (const float4*)g_X[kin];
    const float4* __restrict__ xp = (const float4*)g_X[kprev];
    float4*       __restrict__ y  = (float4*)g_X[kout];
    int t = threadIdx.x;                       // 0..127 -> float4 group
    int r0 = blockIdx.x * SPMM_RPB;
    int r1 = min(r0 + SPMM_RPB, V);
    for (int r = r0; r < r1; r++) {
        int s = g_rowptr[r], e = g_rowptr[r + 1];
        float4 acc = make_float4(0.f, 0.f, 0.f, 0.f);
        int i = s;
        for (; i + 4 <= e; i += 4) {
            int   c0 = __ldcs(&g_scol[i]),     c1 = __ldcs(&g_scol[i + 1]);
            int   c2 = __ldcs(&g_scol[i + 2]), c3 = __ldcs(&g_scol[i + 3]);
            float w0 = __ldcs(&g_sval[i]),     w1 = __ldcs(&g_sval[i + 1]);
            float w2 = __ldcs(&g_sval[i + 2]), w3 = __ldcs(&g_sval[i + 3]);
            float4 v0 = __ldg(&x[(size_t)c0 * 128 + t]);
            float4 v1 = __ldg(&x[(size_t)c1 * 128 + t]);
            float4 v2 = __ldg(&x[(size_t)c2 * 128 + t]);
            float4 v3 = __ldg(&x[(size_t)c3 * 128 + t]);
            acc.x += w0 * v0.x + w1 * v1.x + w2 * v2.x + w3 * v3.x;
            acc.y += w0 * v0.y + w1 * v1.y + w2 * v2.y + w3 * v3.y;
            acc.z += w0 * v0.z + w1 * v1.z + w2 * v2.z + w3 * v3.z;
            acc.w += w0 * v0.w + w1 * v1.w + w2 * v2.w + w3 * v3.w;
        }
        for (; i < e; i++) {
            int   c = __ldcs(&g_scol[i]);
            float w = __ldcs(&g_sval[i]);
            float4 v = __ldg(&x[(size_t)c * 128 + t]);
            acc.x += w * v.x; acc.y += w * v.y;
            acc.z += w * v.z; acc.w += w * v.w;
        }
        size_t oi = (size_t)r * 128 + t;
        if (cheb) {
            float4 p = __ldcs(&xp[oi]);
            acc.x = 2.f * acc.x - p.x; acc.y = 2.f * acc.y - p.y;
            acc.z = 2.f * acc.z - p.z; acc.w = 2.f * acc.w - p.w;
        }
        __stcs(&y[oi], acc);
    }
}

// ---------------- packed f32x2 FMA helpers ---------------------------------
__device__ __forceinline__ void ffma2(unsigned long long& d,
                                      unsigned long long a,
                                      unsigned long long b) {
    asm("fma.rn.f32x2 %0, %1, %2, %0;" : "+l"(d) : "l"(a), "l"(b));
}
__device__ __forceinline__ unsigned long long dup_f32(float a) {
    unsigned long long r;
    asm("mov.b64 %0, {%1, %1};" : "=l"(r) : "f"(a));
    return r;
}
__device__ __forceinline__ void unpack_f32x2(unsigned long long p, float& lo, float& hi) {
    asm("mov.b64 {%0, %1}, %2;" : "=f"(lo), "=f"(hi) : "l"(p));
}

// ---------------- GEMM: out[b*V+v][fo] = sum_{k,fin} X[k][v][fin*4+b] * W[(fin*5+k)*128+fo]
// Block tile: 128 rows (= 4 batches x 32 vertices) x 128 cols, K-step 8.
// Inner product uses packed FFMA2 (2 FMAs/issue) along the j axis.
__global__ void __launch_bounds__(256, 1) gemm_kernel(const float* __restrict__ Wt,
                                                      const float* __restrict__ bias,
                                                      float* __restrict__ out) {
    __shared__ float As[8][132];
    __shared__ float Bs[8][132];   // row stride 528B: 16B-aligned at tx*8
    int t = threadIdx.x;
    int tx = t & 15, ty = t >> 4;
    int v0 = blockIdx.x * 32;

    unsigned long long acc2[8][4];
#pragma unroll
    for (int i = 0; i < 8; i++)
#pragma unroll
        for (int j = 0; j < 4; j++) acc2[i][j] = 0ULL;

    int vl_ld = t >> 3, q_ld = t & 7;           // A-tile loader coords
    int vload = min(v0 + vl_ld, V - 1);
    int jr = t >> 5, c4 = t & 31;               // B-tile loader coords

    for (int kc = 0; kc < KCH; kc++) {
        const float* __restrict__ X = g_X[kc];
        for (int f0 = 0; f0 < FIN; f0 += 8) {
            // global loads: A = 32 vertices x (8 fin x 4 b contiguous floats)
            float4 a = *(const float4*)&X[(size_t)vload * C + (f0 + q_ld) * 4];
            float4 b = *(const float4*)&Wt[(size_t)((f0 + jr) * 5 + kc) * FOUT + c4 * 4];
            __syncthreads();
            As[q_ld][vl_ld]      = a.x;   // b=0
            As[q_ld][32 + vl_ld] = a.y;   // b=1
            As[q_ld][64 + vl_ld] = a.z;   // b=2
            As[q_ld][96 + vl_ld] = a.w;   // b=3
            *(float4*)&Bs[jr][c4 * 4] = b;
            __syncthreads();
#pragma unroll
            for (int p = 0; p < 8; p++) {
                float ar[8];
                *(float4*)&ar[0] = *(const float4*)&As[p][ty * 8];
                *(float4*)&ar[4] = *(const float4*)&As[p][ty * 8 + 4];
                // b pairs: 2 x 16B shared loads, already packed (j, j+1)
                unsigned long long b2[4];
                double2 t0 = *(const double2*)&Bs[p][tx * 8];
                double2 t1 = *(const double2*)&Bs[p][tx * 8 + 4];
                b2[0] = __double_as_longlong(t0.x);
                b2[1] = __double_as_longlong(t0.y);
                b2[2] = __double_as_longlong(t1.x);
                b2[3] = __double_as_longlong(t1.y);
#pragma unroll
                for (int i = 0; i < 8; i++) {
                    unsigned long long a2 = dup_f32(ar[i]);
                    ffma2(acc2[i][0], a2, b2[0]);
                    ffma2(acc2[i][1], a2, b2[1]);
                    ffma2(acc2[i][2], a2, b2[2]);
                    ffma2(acc2[i][3], a2, b2[3]);
                }
            }
        }
    }

    float bs_reg[8];
#pragma unroll
    for (int j = 0; j < 8; j++) bs_reg[j] = bias[tx * 8 + j];

#pragma unroll
    for (int i = 0; i < 8; i++) {
        int rr = ty * 8 + i;
        int bb = rr >> 5, vl = rr & 31;
        int v = v0 + vl;
        if (v < V) {
            size_t base = ((size_t)bb * V + v) * FOUT + tx * 8;
            float o[8];
#pragma unroll
            for (int j2 = 0; j2 < 4; j2++)
                unpack_f32x2(acc2[i][j2], o[2 * j2], o[2 * j2 + 1]);
            float4 o0, o1;
            o0.x = o[0] + bs_reg[0]; o0.y = o[1] + bs_reg[1];
            o0.z = o[2] + bs_reg[2]; o0.w = o[3] + bs_reg[3];
            o1.x = o[4] + bs_reg[4]; o1.y = o[5] + bs_reg[5];
            o1.z = o[6] + bs_reg[6]; o1.w = o[7] + bs_reg[7];
            *(float4*)&out[base]     = o0;
            *(float4*)&out[base + 4] = o1;
        }
    }
}

// ---------------- launcher -------------------------------------------------
extern "C" void kernel_launch(void* const* d_in, const int* in_sizes, int n_in,
                              void* d_out, int out_size) {
    const int*   rows   = (const int*)d_in[0];
    const int*   cols   = (const int*)d_in[1];
    const float* vals   = (const float*)d_in[2];
    const float* inputs = (const float*)d_in[3];
    const float* weight = (const float*)d_in[4];
    const float* bias   = (const float*)d_in[5];
    float*       out    = (float*)d_out;

    zero_kernel<<<(V + 255) / 256, 256>>>();
    hist_kernel<<<(NNZ + 255) / 256, 256>>>(rows);
    scan_kernel<<<1, 1024>>>();
    scatter_kernel<<<(NNZ + 255) / 256, 256>>>(rows, cols, vals);
    transpose_kernel<<<(V * FIN + 255) / 256, 256>>>(inputs);

    for (int k = 1; k < KCH; k++) {
        int kprev = (k >= 2) ? k - 2 : 0;
        int cheb  = (k >= 2) ? 1 : 0;
        spmm_kernel<<<(V + SPMM_RPB - 1) / SPMM_RPB, 128>>>(k, k - 1, kprev, cheb);
    }

    gemm_kernel<<<(V + 31) / 32, 256>>>(weight, bias, out);
}

// round 5
// speedup vs baseline: 1.7276x; 1.1935x over previous
#include <cuda_runtime.h>
#include <cuda_fp16.h>

#define V 50000
#define NNZ 1600000
#define NB 4
#define FIN 128
#define FOUT 128
#define KCH 5
#define C 512           // FIN * NB, row width of dense X
#define SPMM_RPB 2      // rows per block in spmm

// ---------------- scratch (static device globals; no allocation allowed) ----
__device__ float  g_X[KCH][(size_t)V * C];     // fp32 Chebyshev basis (GEMM + cheb-sub)
__device__ __half g_Xh[4][(size_t)V * C];      // fp16 gather mirror (only k=0..3 gathered)
__device__ int    g_count[V];
__device__ int    g_cursor[V];
__device__ int    g_rowptr[V + 1];
__device__ int    g_scol[NNZ];
__device__ float  g_sval[NNZ];

// ---------------- CSR build ------------------------------------------------
__global__ void zero_kernel() {
    int i = blockIdx.x * blockDim.x + threadIdx.x;
    if (i < V) { g_count[i] = 0; g_cursor[i] = 0; }
}

__global__ void hist_kernel(const int* __restrict__ rows) {
    int i = blockIdx.x * blockDim.x + threadIdx.x;
    if (i < NNZ) atomicAdd(&g_count[rows[i]], 1);
}

// single-block exclusive scan over g_count -> g_rowptr
__global__ void scan_kernel() {
    __shared__ int warp_sums[32];
    __shared__ int s_carry;
    int tid = threadIdx.x, lane = tid & 31, wid = tid >> 5;
    if (tid == 0) s_carry = 0;
    __syncthreads();
    const int ntiles = (V + 1023) / 1024;
    for (int t = 0; t < ntiles; t++) {
        int carry = s_carry;
        int i = t * 1024 + tid;
        int v = (i < V) ? g_count[i] : 0;
        int x = v;
#pragma unroll
        for (int o = 1; o < 32; o <<= 1) {
            int n = __shfl_up_sync(0xFFFFFFFFu, x, o);
            if (lane >= o) x += n;
        }
        if (lane == 31) warp_sums[wid] = x;
        __syncthreads();
        if (wid == 0) {
            int s = warp_sums[lane];
#pragma unroll
            for (int o = 1; o < 32; o <<= 1) {
                int n = __shfl_up_sync(0xFFFFFFFFu, s, o);
                if (lane >= o) s += n;
            }
            warp_sums[lane] = s;
        }
        __syncthreads();
        int excl = carry + (x - v) + (wid > 0 ? warp_sums[wid - 1] : 0);
        if (i < V) g_rowptr[i] = excl;
        __syncthreads();
        if (tid == 0) s_carry = carry + warp_sums[31];
        __syncthreads();
    }
    if (threadIdx.x == 0) g_rowptr[V] = s_carry;
}

__global__ void scatter_kernel(const int* __restrict__ rows,
                               const int* __restrict__ cols,
                               const float* __restrict__ vals) {
    int i = blockIdx.x * blockDim.x + threadIdx.x;
    if (i < NNZ) {
        int r = rows[i];
        int p = g_rowptr[r] + atomicAdd(&g_cursor[r], 1);
        g_scol[p] = cols[i];
        g_sval[p] = vals[i];
    }
}

// ---- pack float4 -> 2x half2 (as uint2) -----------------------------------
__device__ __forceinline__ uint2 pack_h4(float4 a) {
    __half2 h0 = __floats2half2_rn(a.x, a.y);
    __half2 h1 = __floats2half2_rn(a.z, a.w);
    uint2 r;
    r.x = *reinterpret_cast<unsigned*>(&h0);
    r.y = *reinterpret_cast<unsigned*>(&h1);
    return r;
}

// ---------------- transpose: inputs[b][v][f] -> X0[v][f*4+b] (+fp16 mirror)
__global__ void transpose_kernel(const float* __restrict__ inp) {
    int i = blockIdx.x * blockDim.x + threadIdx.x;
    if (i < V * FIN) {
        int v = i >> 7, f = i & 127;
        const size_t VF = (size_t)V * FIN;
        float4 o;
        o.x = inp[(size_t)v * FIN + f];
        o.y = inp[VF + (size_t)v * FIN + f];
        o.z = inp[2 * VF + (size_t)v * FIN + f];
        o.w = inp[3 * VF + (size_t)v * FIN + f];
        *(float4*)&g_X[0][(size_t)v * C + f * 4] = o;
        ((uint2*)g_Xh[0])[(size_t)v * 128 + f] = pack_h4(o);
    }
}

// ---------------- SpMM: y = L*x  (or y = 2*L*x - xprev), full 512-col width
// Gathers from the fp16 mirror (1024B/edge instead of 2048B), accumulates
// fp32, writes fp32 y (+fp16 mirror for the next gather).
// 128 threads/block; thread t owns cols [4t, 4t+4) = one uint2 of the mirror.
__global__ void __launch_bounds__(128) spmm_kernel(int kout, int kin, int kprev, int cheb) {
    const uint2*  __restrict__ xh = (const uint2*)g_Xh[kin];
    const float4* __restrict__ xp = (const float4*)g_X[kprev];
    float4*       __restrict__ y  = (float4*)g_X[kout];
    uint2*        __restrict__ yh = (kout < 4) ? (uint2*)g_Xh[kout] : (uint2*)0;
    int t = threadIdx.x;
    int r0 = blockIdx.x * SPMM_RPB;
    int r1 = min(r0 + SPMM_RPB, V);
    for (int r = r0; r < r1; r++) {
        int s = g_rowptr[r], e = g_rowptr[r + 1];
        float4 acc = make_float4(0.f, 0.f, 0.f, 0.f);
        int i = s;
        for (; i + 4 <= e; i += 4) {
            int   c0 = __ldcs(&g_scol[i]),     c1 = __ldcs(&g_scol[i + 1]);
            int   c2 = __ldcs(&g_scol[i + 2]), c3 = __ldcs(&g_scol[i + 3]);
            float w0 = __ldcs(&g_sval[i]),     w1 = __ldcs(&g_sval[i + 1]);
            float w2 = __ldcs(&g_sval[i + 2]), w3 = __ldcs(&g_sval[i + 3]);
            uint2 h0 = __ldg(&xh[(size_t)c0 * 128 + t]);
            uint2 h1 = __ldg(&xh[(size_t)c1 * 128 + t]);
            uint2 h2 = __ldg(&xh[(size_t)c2 * 128 + t]);
            uint2 h3 = __ldg(&xh[(size_t)c3 * 128 + t]);
            float2 a0 = __half22float2(*reinterpret_cast<__half2*>(&h0.x));
            float2 b0 = __half22float2(*reinterpret_cast<__half2*>(&h0.y));
            float2 a1 = __half22float2(*reinterpret_cast<__half2*>(&h1.x));
            float2 b1 = __half22float2(*reinterpret_cast<__half2*>(&h1.y));
            float2 a2 = __half22float2(*reinterpret_cast<__half2*>(&h2.x));
            float2 b2 = __half22float2(*reinterpret_cast<__half2*>(&h2.y));
            float2 a3 = __half22float2(*reinterpret_cast<__half2*>(&h3.x));
            float2 b3 = __half22float2(*reinterpret_cast<__half2*>(&h3.y));
            acc.x += w0 * a0.x + w1 * a1.x + w2 * a2.x + w3 * a3.x;
            acc.y += w0 * a0.y + w1 * a1.y + w2 * a2.y + w3 * a3.y;
            acc.z += w0 * b0.x + w1 * b1.x + w2 * b2.x + w3 * b3.x;
            acc.w += w0 * b0.y + w1 * b1.y + w2 * b2.y + w3 * b3.y;
        }
        for (; i < e; i++) {
            int   c = __ldcs(&g_scol[i]);
            float w = __ldcs(&g_sval[i]);
            uint2 h = __ldg(&xh[(size_t)c * 128 + t]);
            float2 a = __half22float2(*reinterpret_cast<__half2*>(&h.x));
            float2 b = __half22float2(*reinterpret_cast<__half2*>(&h.y));
            acc.x += w * a.x; acc.y += w * a.y;
            acc.z += w * b.x; acc.w += w * b.y;
        }
        size_t oi = (size_t)r * 128 + t;
        if (cheb) {
            float4 p = __ldcs(&xp[oi]);
            acc.x = 2.f * acc.x - p.x; acc.y = 2.f * acc.y - p.y;
            acc.z = 2.f * acc.z - p.z; acc.w = 2.f * acc.w - p.w;
        }
        __stcs(&y[oi], acc);
        if (yh) yh[oi] = pack_h4(acc);   // keep mirror L2-resident for next gather
    }
}

// ---------------- packed f32x2 FMA helpers ---------------------------------
__device__ __forceinline__ void ffma2(unsigned long long& d,
                                      unsigned long long a,
                                      unsigned long long b) {
    asm("fma.rn.f32x2 %0, %1, %2, %0;" : "+l"(d) : "l"(a), "l"(b));
}
__device__ __forceinline__ unsigned long long dup_f32(float a) {
    unsigned long long r;
    asm("mov.b64 %0, {%1, %1};" : "=l"(r) : "f"(a));
    return r;
}
__device__ __forceinline__ void unpack_f32x2(unsigned long long p, float& lo, float& hi) {
    asm("mov.b64 {%0, %1}, %2;" : "=f"(lo), "=f"(hi) : "l"(p));
}

// ---------------- GEMM: out[b*V+v][fo] = sum_{k,fin} X[k][v][fin*4+b] * W[(fin*5+k)*128+fo]
// Block tile: 128 rows (= 4 batches x 32 vertices) x 128 cols, K-step 8.
// Inner product uses packed FFMA2 (2 FMAs/issue) along the j axis.
__global__ void __launch_bounds__(256, 1) gemm_kernel(const float* __restrict__ Wt,
                                                      const float* __restrict__ bias,
                                                      float* __restrict__ out) {
    __shared__ float As[8][132];
    __shared__ float Bs[8][132];   // row stride 528B: 16B-aligned at tx*8
    int t = threadIdx.x;
    int tx = t & 15, ty = t >> 4;
    int v0 = blockIdx.x * 32;

    unsigned long long acc2[8][4];
#pragma unroll
    for (int i = 0; i < 8; i++)
#pragma unroll
        for (int j = 0; j < 4; j++) acc2[i][j] = 0ULL;

    int vl_ld = t >> 3, q_ld = t & 7;           // A-tile loader coords
    int vload = min(v0 + vl_ld, V - 1);
    int jr = t >> 5, c4 = t & 31;               // B-tile loader coords

    for (int kc = 0; kc < KCH; kc++) {
        const float* __restrict__ X = g_X[kc];
        for (int f0 = 0; f0 < FIN; f0 += 8) {
            // global loads: A = 32 vertices x (8 fin x 4 b contiguous floats)
            float4 a = *(const float4*)&X[(size_t)vload * C + (f0 + q_ld) * 4];
            float4 b = *(const float4*)&Wt[(size_t)((f0 + jr) * 5 + kc) * FOUT + c4 * 4];
            __syncthreads();
            As[q_ld][vl_ld]      = a.x;   // b=0
            As[q_ld][32 + vl_ld] = a.y;   // b=1
            As[q_ld][64 + vl_ld] = a.z;   // b=2
            As[q_ld][96 + vl_ld] = a.w;   // b=3
            *(float4*)&Bs[jr][c4 * 4] = b;
            __syncthreads();
#pragma unroll
            for (int p = 0; p < 8; p++) {
                float ar[8];
                *(float4*)&ar[0] = *(const float4*)&As[p][ty * 8];
                *(float4*)&ar[4] = *(const float4*)&As[p][ty * 8 + 4];
                // b pairs: 2 x 16B shared loads, already packed (j, j+1)
                unsigned long long b2[4];
                double2 t0 = *(const double2*)&Bs[p][tx * 8];
                double2 t1 = *(const double2*)&Bs[p][tx * 8 + 4];
                b2[0] = __double_as_longlong(t0.x);
                b2[1] = __double_as_longlong(t0.y);
                b2[2] = __double_as_longlong(t1.x);
                b2[3] = __double_as_longlong(t1.y);
#pragma unroll
                for (int i = 0; i < 8; i++) {
                    unsigned long long a2 = dup_f32(ar[i]);
                    ffma2(acc2[i][0], a2, b2[0]);
                    ffma2(acc2[i][1], a2, b2[1]);
                    ffma2(acc2[i][2], a2, b2[2]);
                    ffma2(acc2[i][3], a2, b2[3]);
                }
            }
        }
    }

    float bs_reg[8];
#pragma unroll
    for (int j = 0; j < 8; j++) bs_reg[j] = bias[tx * 8 + j];

#pragma unroll
    for (int i = 0; i < 8; i++) {
        int rr = ty * 8 + i;
        int bb = rr >> 5, vl = rr & 31;
        int v = v0 + vl;
        if (v < V) {
            size_t base = ((size_t)bb * V + v) * FOUT + tx * 8;
            float o[8];
#pragma unroll
            for (int j2 = 0; j2 < 4; j2++)
                unpack_f32x2(acc2[i][j2], o[2 * j2], o[2 * j2 + 1]);
            float4 o0, o1;
            o0.x = o[0] + bs_reg[0]; o0.y = o[1] + bs_reg[1];
            o0.z = o[2] + bs_reg[2]; o0.w = o[3] + bs_reg[3];
            o1.x = o[4] + bs_reg[4]; o1.y = o[5] + bs_reg[5];
            o1.z = o[6] + bs_reg[6]; o1.w = o[7] + bs_reg[7];
            *(float4*)&out[base]     = o0;
            *(float4*)&out[base + 4] = o1;
        }
    }
}

// ---------------- launcher -------------------------------------------------
extern "C" void kernel_launch(void* const* d_in, const int* in_sizes, int n_in,
                              void* d_out, int out_size) {
    const int*   rows   = (const int*)d_in[0];
    const int*   cols   = (const int*)d_in[1];
    const float* vals   = (const float*)d_in[2];
    const float* inputs = (const float*)d_in[3];
    const float* weight = (const float*)d_in[4];
    const float* bias   = (const float*)d_in[5];
    float*       out    = (float*)d_out;

    zero_kernel<<<(V + 255) / 256, 256>>>();
    hist_kernel<<<(NNZ + 255) / 256, 256>>>(rows);
    scan_kernel<<<1, 1024>>>();
    scatter_kernel<<<(NNZ + 255) / 256, 256>>>(rows, cols, vals);
    transpose_kernel<<<(V * FIN + 255) / 256, 256>>>(inputs);

    for (int k = 1; k < KCH; k++) {
        int kprev = (k >= 2) ? k - 2 : 0;
        int cheb  = (k >= 2) ? 1 : 0;
        spmm_kernel<<<(V + SPMM_RPB - 1) / SPMM_RPB, 128>>>(k, k - 1, kprev, cheb);
    }

    gemm_kernel<<<(V + 31) / 32, 256>>>(weight, bias, out);
}

// round 6
// speedup vs baseline: 2.7208x; 1.5749x over previous
#include <cuda_runtime.h>
#include <cuda_fp16.h>

#define V 50000
#define NNZ 1600000
#define NB 4
#define FIN 128
#define FOUT 128
#define KCH 5
#define C 512           // FIN * NB, row width of dense X
#define SPMM_RPB 2      // rows per block in spmm

// ---------------- scratch (static device globals; no allocation allowed) ----
__device__ float  g_X[KCH][(size_t)V * C];     // fp32 Chebyshev basis (cheb-sub master)
__device__ __half g_Xh[4][(size_t)V * C];      // fp16 gather mirror (k=0..3 gathered)
// GEMM-layout fp16 A: [(kc*4+b)*4 + fin_chunk][v][32]  (chunked so each K-chunk is contiguous)
__device__ __half g_Ah[(size_t)KCH * NB * 4 * V * 32];
__device__ __half g_Wh[KCH * FIN * FOUT];      // [k][fin][fo] fp16 weights
__device__ int    g_count[V];
__device__ int    g_cursor[V];
__device__ int    g_rowptr[V + 1];
__device__ int    g_scol[NNZ];
__device__ float  g_sval[NNZ];

// ---------------- CSR build ------------------------------------------------
__global__ void zero_kernel() {
    int i = blockIdx.x * blockDim.x + threadIdx.x;
    if (i < V) { g_count[i] = 0; g_cursor[i] = 0; }
}

__global__ void hist_kernel(const int* __restrict__ rows) {
    int i = blockIdx.x * blockDim.x + threadIdx.x;
    if (i < NNZ) atomicAdd(&g_count[rows[i]], 1);
}

// single-block exclusive scan over g_count -> g_rowptr
__global__ void scan_kernel() {
    __shared__ int warp_sums[32];
    __shared__ int s_carry;
    int tid = threadIdx.x, lane = tid & 31, wid = tid >> 5;
    if (tid == 0) s_carry = 0;
    __syncthreads();
    const int ntiles = (V + 1023) / 1024;
    for (int t = 0; t < ntiles; t++) {
        int carry = s_carry;
        int i = t * 1024 + tid;
        int v = (i < V) ? g_count[i] : 0;
        int x = v;
#pragma unroll
        for (int o = 1; o < 32; o <<= 1) {
            int n = __shfl_up_sync(0xFFFFFFFFu, x, o);
            if (lane >= o) x += n;
        }
        if (lane == 31) warp_sums[wid] = x;
        __syncthreads();
        if (wid == 0) {
            int s = warp_sums[lane];
#pragma unroll
            for (int o = 1; o < 32; o <<= 1) {
                int n = __shfl_up_sync(0xFFFFFFFFu, s, o);
                if (lane >= o) s += n;
            }
            warp_sums[lane] = s;
        }
        __syncthreads();
        int excl = carry + (x - v) + (wid > 0 ? warp_sums[wid - 1] : 0);
        if (i < V) g_rowptr[i] = excl;
        __syncthreads();
        if (tid == 0) s_carry = carry + warp_sums[31];
        __syncthreads();
    }
    if (threadIdx.x == 0) g_rowptr[V] = s_carry;
}

__global__ void scatter_kernel(const int* __restrict__ rows,
                               const int* __restrict__ cols,
                               const float* __restrict__ vals) {
    int i = blockIdx.x * blockDim.x + threadIdx.x;
    if (i < NNZ) {
        int r = rows[i];
        int p = g_rowptr[r] + atomicAdd(&g_cursor[r], 1);
        g_scol[p] = cols[i];
        g_sval[p] = vals[i];
    }
}

// ---- pack float4 -> 2x half2 (as uint2) -----------------------------------
__device__ __forceinline__ uint2 pack_h4(float4 a) {
    __half2 h0 = __floats2half2_rn(a.x, a.y);
    __half2 h1 = __floats2half2_rn(a.z, a.w);
    uint2 r;
    r.x = *reinterpret_cast<unsigned*>(&h0);
    r.y = *reinterpret_cast<unsigned*>(&h1);
    return r;
}

// write GEMM-layout planes: value (fin=f, b) for vertex v, order k
__device__ __forceinline__ void store_planes(int k, int v, int f, float4 a) {
    int ch = f >> 5, fi = f & 31;
    float vb[4] = {a.x, a.y, a.z, a.w};
#pragma unroll
    for (int b = 0; b < 4; b++) {
        size_t idx = (((size_t)(k * 4 + b) * 4 + ch) * V + v) * 32 + fi;
        g_Ah[idx] = __float2half(vb[b]);
    }
}

// ---------------- transpose: inputs[b][v][f] -> X0[v][f*4+b] (+fp16 copies)
__global__ void transpose_kernel(const float* __restrict__ inp) {
    int i = blockIdx.x * blockDim.x + threadIdx.x;
    if (i < V * FIN) {
        int v = i >> 7, f = i & 127;
        const size_t VF = (size_t)V * FIN;
        float4 o;
        o.x = inp[(size_t)v * FIN + f];
        o.y = inp[VF + (size_t)v * FIN + f];
        o.z = inp[2 * VF + (size_t)v * FIN + f];
        o.w = inp[3 * VF + (size_t)v * FIN + f];
        *(float4*)&g_X[0][(size_t)v * C + f * 4] = o;
        ((uint2*)g_Xh[0])[(size_t)v * 128 + f] = pack_h4(o);
        store_planes(0, v, f, o);
    }
}

// ---------------- weight fp16 conversion: g_Wh[k][fin][fo] ------------------
__global__ void wconv_kernel(const float* __restrict__ Wt) {
    int i = blockIdx.x * blockDim.x + threadIdx.x;
    if (i < KCH * FIN * FOUT) {
        int k = i / (FIN * FOUT), fin = (i / FOUT) % FIN, fo = i % FOUT;
        g_Wh[i] = __float2half(Wt[(size_t)(fin * KCH + k) * FOUT + fo]);
    }
}

// ---------------- SpMM: y = L*x  (or y = 2*L*x - xprev), full 512-col width
// Gathers fp16 mirror (1024B/edge), fp32 accumulate, writes fp32 master +
// fp16 mirror + fp16 GEMM planes.
__global__ void __launch_bounds__(128) spmm_kernel(int kout, int kin, int kprev, int cheb) {
    const uint2*  __restrict__ xh = (const uint2*)g_Xh[kin];
    const float4* __restrict__ xp = (const float4*)g_X[kprev];
    float4*       __restrict__ y  = (float4*)g_X[kout];
    uint2*        __restrict__ yh = (kout < 4) ? (uint2*)g_Xh[kout] : (uint2*)0;
    int t = threadIdx.x;
    int r0 = blockIdx.x * SPMM_RPB;
    int r1 = min(r0 + SPMM_RPB, V);
    for (int r = r0; r < r1; r++) {
        int s = g_rowptr[r], e = g_rowptr[r + 1];
        float4 acc = make_float4(0.f, 0.f, 0.f, 0.f);
        int i = s;
        for (; i + 4 <= e; i += 4) {
            int   c0 = __ldcs(&g_scol[i]),     c1 = __ldcs(&g_scol[i + 1]);
            int   c2 = __ldcs(&g_scol[i + 2]), c3 = __ldcs(&g_scol[i + 3]);
            float w0 = __ldcs(&g_sval[i]),     w1 = __ldcs(&g_sval[i + 1]);
            float w2 = __ldcs(&g_sval[i + 2]), w3 = __ldcs(&g_sval[i + 3]);
            uint2 h0 = __ldg(&xh[(size_t)c0 * 128 + t]);
            uint2 h1 = __ldg(&xh[(size_t)c1 * 128 + t]);
            uint2 h2 = __ldg(&xh[(size_t)c2 * 128 + t]);
            uint2 h3 = __ldg(&xh[(size_t)c3 * 128 + t]);
            float2 a0 = __half22float2(*reinterpret_cast<__half2*>(&h0.x));
            float2 b0 = __half22float2(*reinterpret_cast<__half2*>(&h0.y));
            float2 a1 = __half22float2(*reinterpret_cast<__half2*>(&h1.x));
            float2 b1 = __half22float2(*reinterpret_cast<__half2*>(&h1.y));
            float2 a2 = __half22float2(*reinterpret_cast<__half2*>(&h2.x));
            float2 b2 = __half22float2(*reinterpret_cast<__half2*>(&h2.y));
            float2 a3 = __half22float2(*reinterpret_cast<__half2*>(&h3.x));
            float2 b3 = __half22float2(*reinterpret_cast<__half2*>(&h3.y));
            acc.x += w0 * a0.x + w1 * a1.x + w2 * a2.x + w3 * a3.x;
            acc.y += w0 * a0.y + w1 * a1.y + w2 * a2.y + w3 * a3.y;
            acc.z += w0 * b0.x + w1 * b1.x + w2 * b2.x + w3 * b3.x;
            acc.w += w0 * b0.y + w1 * b1.y + w2 * b2.y + w3 * b3.y;
        }
        for (; i < e; i++) {
            int   c = __ldcs(&g_scol[i]);
            float w = __ldcs(&g_sval[i]);
            uint2 h = __ldg(&xh[(size_t)c * 128 + t]);
            float2 a = __half22float2(*reinterpret_cast<__half2*>(&h.x));
            float2 b = __half22float2(*reinterpret_cast<__half2*>(&h.y));
            acc.x += w * a.x; acc.y += w * a.y;
            acc.z += w * b.x; acc.w += w * b.y;
        }
        size_t oi = (size_t)r * 128 + t;
        if (cheb) {
            float4 p = __ldcs(&xp[oi]);
            acc.x = 2.f * acc.x - p.x; acc.y = 2.f * acc.y - p.y;
            acc.z = 2.f * acc.z - p.z; acc.w = 2.f * acc.w - p.w;
        }
        __stcs(&y[oi], acc);
        if (yh) yh[oi] = pack_h4(acc);   // mirror for next gather
        store_planes(kout, r, t, acc);   // GEMM layout copy
    }
}

// ---------------- mma helpers ----------------------------------------------
__device__ __forceinline__ unsigned smem_u32(const void* p) {
    return (unsigned)__cvta_generic_to_shared(p);
}
__device__ __forceinline__ void ldmatrix_x4(unsigned* r, unsigned a) {
    asm volatile("ldmatrix.sync.aligned.m8n8.x4.shared.b16 {%0,%1,%2,%3}, [%4];"
                 : "=r"(r[0]), "=r"(r[1]), "=r"(r[2]), "=r"(r[3]) : "r"(a));
}
__device__ __forceinline__ void ldmatrix_x2t(unsigned* r, unsigned a) {
    asm volatile("ldmatrix.sync.aligned.m8n8.x2.trans.shared.b16 {%0,%1}, [%2];"
                 : "=r"(r[0]), "=r"(r[1]) : "r"(a));
}
__device__ __forceinline__ void mma16816(float* d, const unsigned* a, const unsigned* b) {
    asm volatile("mma.sync.aligned.m16n8k16.row.col.f32.f16.f16.f32 "
                 "{%0,%1,%2,%3},{%4,%5,%6,%7},{%8,%9},{%0,%1,%2,%3};"
                 : "+f"(d[0]), "+f"(d[1]), "+f"(d[2]), "+f"(d[3])
                 : "r"(a[0]), "r"(a[1]), "r"(a[2]), "r"(a[3]),
                   "r"(b[0]), "r"(b[1]));
}

// ---------------- GEMM (tensor cores): per (v-tile, b) block ----------------
// out[b*V+v][fo] = sum_{k,fin} Ah[k][b][v][fin] * Wh[k][fin][fo] + bias
// Block 128x128, 8 warps (4m x 2n) each 32x64, K=640 in 20 chunks of 32.
__global__ void __launch_bounds__(256) gemm_kernel(const float* __restrict__ bias,
                                                   float* __restrict__ out) {
    __shared__ __half As[128][40];   // 32 used + 8 pad (row 80B, 16B-aligned)
    __shared__ __half Bs[32][136];   // 128 used + 8 pad (row 272B, 16B-aligned)
    int t = threadIdx.x, lane = t & 31, wid = t >> 5;
    int wm = wid >> 1, wn = wid & 1;
    int v0 = blockIdx.x * 128;
    int b  = blockIdx.y;

    float acc[2][8][4];
#pragma unroll
    for (int am = 0; am < 2; am++)
#pragma unroll
        for (int nt = 0; nt < 8; nt++)
#pragma unroll
            for (int q = 0; q < 4; q++) acc[am][nt][q] = 0.f;

    for (int kc = 0; kc < KCH; kc++) {
#pragma unroll 1
        for (int ch = 0; ch < 4; ch++) {
            const __half* Ap = g_Ah + ((size_t)(kc * 4 + b) * 4 + ch) * ((size_t)V * 32);
            const __half* Bp = g_Wh + ((size_t)kc * FIN + ch * 32) * FOUT;
#pragma unroll
            for (int j = 0; j < 2; j++) {
                int u = t + j * 256;               // uint4 (8-half) index
                int row = u >> 2, seg = u & 3;     // A: 4 segs of 8 halves per row
                int vv = min(v0 + row, V - 1);
                uint4 val = *(const uint4*)(Ap + (size_t)vv * 32 + seg * 8);
                *(uint4*)&As[row][seg * 8] = val;
            }
#pragma unroll
            for (int j = 0; j < 2; j++) {
                int u = t + j * 256;
                int row = u >> 4, seg = u & 15;    // B: 16 segs per 128-half row
                uint4 val = *(const uint4*)(Bp + row * FOUT + seg * 8);
                *(uint4*)&Bs[row][seg * 8] = val;
            }
            __syncthreads();
#pragma unroll
            for (int ks = 0; ks < 32; ks += 16) {
                unsigned af[2][4], bf[8][2];
#pragma unroll
                for (int am = 0; am < 2; am++) {
                    int m = wm * 32 + am * 16 + (lane & 15);
                    int col = ks + (lane >> 4) * 8;
                    ldmatrix_x4(af[am], smem_u32(&As[m][col]));
                }
#pragma unroll
                for (int nt = 0; nt < 8; nt++) {
                    int row = ks + (lane & 15);
                    int n = wn * 64 + nt * 8;
                    ldmatrix_x2t(bf[nt], smem_u32(&Bs[row][n]));
                }
#pragma unroll
                for (int am = 0; am < 2; am++)
#pragma unroll
                    for (int nt = 0; nt < 8; nt++)
                        mma16816(acc[am][nt], af[am], bf[nt]);
            }
            __syncthreads();
        }
    }

    // epilogue: d0,d1 -> row r, cols c,c+1 ; d2,d3 -> row r+8
#pragma unroll
    for (int am = 0; am < 2; am++) {
        int r = v0 + wm * 32 + am * 16 + (lane >> 2);
#pragma unroll
        for (int nt = 0; nt < 8; nt++) {
            int col = wn * 64 + nt * 8 + (lane & 3) * 2;
            float2 bv = *(const float2*)&bias[col];
            if (r < V) {
                float2 o = make_float2(acc[am][nt][0] + bv.x, acc[am][nt][1] + bv.y);
                *(float2*)&out[((size_t)b * V + r) * FOUT + col] = o;
            }
            if (r + 8 < V) {
                float2 o = make_float2(acc[am][nt][2] + bv.x, acc[am][nt][3] + bv.y);
                *(float2*)&out[((size_t)b * V + r + 8) * FOUT + col] = o;
            }
        }
    }
}

// ---------------- launcher -------------------------------------------------
extern "C" void kernel_launch(void* const* d_in, const int* in_sizes, int n_in,
                              void* d_out, int out_size) {
    const int*   rows   = (const int*)d_in[0];
    const int*   cols   = (const int*)d_in[1];
    const float* vals   = (const float*)d_in[2];
    const float* inputs = (const float*)d_in[3];
    const float* weight = (const float*)d_in[4];
    const float* bias   = (const float*)d_in[5];
    float*       out    = (float*)d_out;

    zero_kernel<<<(V + 255) / 256, 256>>>();
    hist_kernel<<<(NNZ + 255) / 256, 256>>>(rows);
    scan_kernel<<<1, 1024>>>();
    scatter_kernel<<<(NNZ + 255) / 256, 256>>>(rows, cols, vals);
    transpose_kernel<<<(V * FIN + 255) / 256, 256>>>(inputs);
    wconv_kernel<<<(KCH * FIN * FOUT + 255) / 256, 256>>>(weight);

    for (int k = 1; k < KCH; k++) {
        int kprev = (k >= 2) ? k - 2 : 0;
        int cheb  = (k >= 2) ? 1 : 0;
        spmm_kernel<<<(V + SPMM_RPB - 1) / SPMM_RPB, 128>>>(k, k - 1, kprev, cheb);
    }

    dim3 ggrid((V + 127) / 128, NB);
    gemm_kernel<<<ggrid, 256>>>(bias, out);
}

// round 7
// speedup vs baseline: 2.9490x; 1.0839x over previous
#include <cuda_runtime.h>
#include <cuda_fp16.h>

#define V 50000
#define NNZ 1600000
#define NB 4
#define FIN 128
#define FOUT 128
#define KCH 5
#define SPMM_RPB 2      // rows per block in spmm

// ---------------- scratch (static device globals; no allocation allowed) ----
// Unified fp16 basis storage, plane-major: [k][b][v][128 fin]
// Serves as: SpMM gather source, Chebyshev xp operand, GEMM A operand.
__device__ __half g_Xh[KCH][NB][(size_t)V * 128];
__device__ __half g_Wh[KCH * FIN * FOUT];      // [k][fin][fo] fp16 weights
__device__ int    g_count[V];
__device__ int    g_cursor[V];
__device__ int    g_rowptr[V + 1];
__device__ int    g_scol[NNZ];
__device__ float  g_sval[NNZ];

// ---------------- CSR build ------------------------------------------------
__global__ void zero_kernel() {
    int i = blockIdx.x * blockDim.x + threadIdx.x;
    if (i < V) { g_count[i] = 0; g_cursor[i] = 0; }
}

__global__ void hist_kernel(const int* __restrict__ rows) {
    int i = blockIdx.x * blockDim.x + threadIdx.x;
    if (i < NNZ) atomicAdd(&g_count[rows[i]], 1);
}

// single-block exclusive scan over g_count -> g_rowptr
__global__ void scan_kernel() {
    __shared__ int warp_sums[32];
    __shared__ int s_carry;
    int tid = threadIdx.x, lane = tid & 31, wid = tid >> 5;
    if (tid == 0) s_carry = 0;
    __syncthreads();
    const int ntiles = (V + 1023) / 1024;
    for (int t = 0; t < ntiles; t++) {
        int carry = s_carry;
        int i = t * 1024 + tid;
        int v = (i < V) ? g_count[i] : 0;
        int x = v;
#pragma unroll
        for (int o = 1; o < 32; o <<= 1) {
            int n = __shfl_up_sync(0xFFFFFFFFu, x, o);
            if (lane >= o) x += n;
        }
        if (lane == 31) warp_sums[wid] = x;
        __syncthreads();
        if (wid == 0) {
            int s = warp_sums[lane];
#pragma unroll
            for (int o = 1; o < 32; o <<= 1) {
                int n = __shfl_up_sync(0xFFFFFFFFu, s, o);
                if (lane >= o) s += n;
            }
            warp_sums[lane] = s;
        }
        __syncthreads();
        int excl = carry + (x - v) + (wid > 0 ? warp_sums[wid - 1] : 0);
        if (i < V) g_rowptr[i] = excl;
        __syncthreads();
        if (tid == 0) s_carry = carry + warp_sums[31];
        __syncthreads();
    }
    if (threadIdx.x == 0) g_rowptr[V] = s_carry;
}

__global__ void scatter_kernel(const int* __restrict__ rows,
                               const int* __restrict__ cols,
                               const float* __restrict__ vals) {
    int i = blockIdx.x * blockDim.x + threadIdx.x;
    if (i < NNZ) {
        int r = rows[i];
        int p = g_rowptr[r] + atomicAdd(&g_cursor[r], 1);
        g_scol[p] = cols[i];
        g_sval[p] = vals[i];
    }
}

// ---- pack float4 -> 2x half2 (as uint2) -----------------------------------
__device__ __forceinline__ uint2 pack_h4(float4 a) {
    __half2 h0 = __floats2half2_rn(a.x, a.y);
    __half2 h1 = __floats2half2_rn(a.z, a.w);
    uint2 r;
    r.x = *reinterpret_cast<unsigned*>(&h0);
    r.y = *reinterpret_cast<unsigned*>(&h1);
    return r;
}
__device__ __forceinline__ float2 h2f(unsigned u) {
    return __half22float2(*reinterpret_cast<__half2*>(&u));
}

// ---------------- transpose: inputs[b][v][f] fp32 -> plane (0,b) fp16 -------
// thread = (b, v, fquad): fully coalesced float4 read + uint2 write.
__global__ void transpose_kernel(const float* __restrict__ inp) {
    int i = blockIdx.x * blockDim.x + threadIdx.x;
    if (i < NB * V * 32) {
        int q = i & 31, v = (i >> 5) % V, b = i / (V * 32);
        float4 o = *(const float4*)&inp[((size_t)b * V + v) * FIN + q * 4];
        ((uint2*)g_Xh[0][b])[(size_t)v * 32 + q] = pack_h4(o);
    }
}

// ---------------- weight fp16 conversion: g_Wh[k][fin][fo] ------------------
__global__ void wconv_kernel(const float* __restrict__ Wt) {
    int i = blockIdx.x * blockDim.x + threadIdx.x;
    if (i < KCH * FIN * FOUT) {
        int k = i / (FIN * FOUT), fin = (i / FOUT) % FIN, fo = i % FOUT;
        g_Wh[i] = __float2half(Wt[(size_t)(fin * KCH + k) * FOUT + fo]);
    }
}

// ---------------- SpMM: y = L*x  (or y = 2*L*x - xprev), full 512-col width
// Plane-major fp16: warp w handles batch plane b=w; thread owns 4 fin cols.
// Per edge per warp: 32 consecutive uint2 = 256B fully coalesced gather.
__global__ void __launch_bounds__(128) spmm_kernel(int kout, int kin, int kprev, int cheb) {
    int t = threadIdx.x;
    int b = t >> 5, q = t & 31;
    const uint2* __restrict__ x  = (const uint2*)g_Xh[kin][b];
    const uint2* __restrict__ xp = (const uint2*)g_Xh[kprev][b];
    uint2*       __restrict__ y  = (uint2*)g_Xh[kout][b];
    int r0 = blockIdx.x * SPMM_RPB;
    int r1 = min(r0 + SPMM_RPB, V);
    for (int r = r0; r < r1; r++) {
        int s = g_rowptr[r], e = g_rowptr[r + 1];
        float4 acc = make_float4(0.f, 0.f, 0.f, 0.f);
        int i = s;
        for (; i + 4 <= e; i += 4) {
            int   c0 = __ldcs(&g_scol[i]),     c1 = __ldcs(&g_scol[i + 1]);
            int   c2 = __ldcs(&g_scol[i + 2]), c3 = __ldcs(&g_scol[i + 3]);
            float w0 = __ldcs(&g_sval[i]),     w1 = __ldcs(&g_sval[i + 1]);
            float w2 = __ldcs(&g_sval[i + 2]), w3 = __ldcs(&g_sval[i + 3]);
            uint2 h0 = __ldg(&x[(size_t)c0 * 32 + q]);
            uint2 h1 = __ldg(&x[(size_t)c1 * 32 + q]);
            uint2 h2 = __ldg(&x[(size_t)c2 * 32 + q]);
            uint2 h3 = __ldg(&x[(size_t)c3 * 32 + q]);
            float2 a0 = h2f(h0.x), b0 = h2f(h0.y);
            float2 a1 = h2f(h1.x), b1 = h2f(h1.y);
            float2 a2 = h2f(h2.x), b2 = h2f(h2.y);
            float2 a3 = h2f(h3.x), b3 = h2f(h3.y);
            acc.x += w0 * a0.x + w1 * a1.x + w2 * a2.x + w3 * a3.x;
            acc.y += w0 * a0.y + w1 * a1.y + w2 * a2.y + w3 * a3.y;
            acc.z += w0 * b0.x + w1 * b1.x + w2 * b2.x + w3 * b3.x;
            acc.w += w0 * b0.y + w1 * b1.y + w2 * b2.y + w3 * b3.y;
        }
        for (; i < e; i++) {
            int   c = __ldcs(&g_scol[i]);
            float w = __ldcs(&g_sval[i]);
            uint2 h = __ldg(&x[(size_t)c * 32 + q]);
            float2 a = h2f(h.x), bb = h2f(h.y);
            acc.x += w * a.x;  acc.y += w * a.y;
            acc.z += w * bb.x; acc.w += w * bb.y;
        }
        size_t oi = (size_t)r * 32 + q;
        if (cheb) {
            uint2 ph = __ldcs(&xp[oi]);
            float2 p0 = h2f(ph.x), p1 = h2f(ph.y);
            acc.x = 2.f * acc.x - p0.x; acc.y = 2.f * acc.y - p0.y;
            acc.z = 2.f * acc.z - p1.x; acc.w = 2.f * acc.w - p1.y;
        }
        __stcs(&y[oi], pack_h4(acc));
    }
}

// ---------------- mma helpers ----------------------------------------------
__device__ __forceinline__ unsigned smem_u32(const void* p) {
    return (unsigned)__cvta_generic_to_shared(p);
}
__device__ __forceinline__ void ldmatrix_x4(unsigned* r, unsigned a) {
    asm volatile("ldmatrix.sync.aligned.m8n8.x4.shared.b16 {%0,%1,%2,%3}, [%4];"
                 : "=r"(r[0]), "=r"(r[1]), "=r"(r[2]), "=r"(r[3]) : "r"(a));
}
__device__ __forceinline__ void ldmatrix_x2t(unsigned* r, unsigned a) {
    asm volatile("ldmatrix.sync.aligned.m8n8.x2.trans.shared.b16 {%0,%1}, [%2];"
                 : "=r"(r[0]), "=r"(r[1]) : "r"(a));
}
__device__ __forceinline__ void mma16816(float* d, const unsigned* a, const unsigned* b) {
    asm volatile("mma.sync.aligned.m16n8k16.row.col.f32.f16.f16.f32 "
                 "{%0,%1,%2,%3},{%4,%5,%6,%7},{%8,%9},{%0,%1,%2,%3};"
                 : "+f"(d[0]), "+f"(d[1]), "+f"(d[2]), "+f"(d[3])
                 : "r"(a[0]), "r"(a[1]), "r"(a[2]), "r"(a[3]),
                   "r"(b[0]), "r"(b[1]));
}

// ---------------- GEMM (tensor cores): per (v-tile, b) block ----------------
// out[b*V+v][fo] = sum_{k,fin} Xh[k][b][v][fin] * Wh[k][fin][fo] + bias
// Block 128x128, 8 warps (4m x 2n) each 32x64, K=640 in 20 chunks of 32.
__global__ void __launch_bounds__(256) gemm_kernel(const float* __restrict__ bias,
                                                   float* __restrict__ out) {
    __shared__ __half As[128][40];   // 32 used + 8 pad
    __shared__ __half Bs[32][136];   // 128 used + 8 pad
    int t = threadIdx.x, lane = t & 31, wid = t >> 5;
    int wm = wid >> 1, wn = wid & 1;
    int v0 = blockIdx.x * 128;
    int b  = blockIdx.y;

    float acc[2][8][4];
#pragma unroll
    for (int am = 0; am < 2; am++)
#pragma unroll
        for (int nt = 0; nt < 8; nt++)
#pragma unroll
            for (int q = 0; q < 4; q++) acc[am][nt][q] = 0.f;

    for (int kc = 0; kc < KCH; kc++) {
        const __half* Aplane = g_Xh[kc][b];
#pragma unroll 1
        for (int ch = 0; ch < 4; ch++) {
            const __half* Bp = g_Wh + ((size_t)kc * FIN + ch * 32) * FOUT;
#pragma unroll
            for (int j = 0; j < 2; j++) {
                int u = t + j * 256;               // uint4 (8-half) index
                int row = u >> 2, seg = u & 3;     // A: 4 segs of 8 halves per row
                int vv = min(v0 + row, V - 1);
                uint4 val = *(const uint4*)(Aplane + (size_t)vv * 128 + ch * 32 + seg * 8);
                *(uint4*)&As[row][seg * 8] = val;
            }
#pragma unroll
            for (int j = 0; j < 2; j++) {
                int u = t + j * 256;
                int row = u >> 4, seg = u & 15;    // B: 16 segs per 128-half row
                uint4 val = *(const uint4*)(Bp + row * FOUT + seg * 8);
                *(uint4*)&Bs[row][seg * 8] = val;
            }
            __syncthreads();
#pragma unroll
            for (int ks = 0; ks < 32; ks += 16) {
                unsigned af[2][4], bf[8][2];
#pragma unroll
                for (int am = 0; am < 2; am++) {
                    int m = wm * 32 + am * 16 + (lane & 15);
                    int col = ks + (lane >> 4) * 8;
                    ldmatrix_x4(af[am], smem_u32(&As[m][col]));
                }
#pragma unroll
                for (int nt = 0; nt < 8; nt++) {
                    int row = ks + (lane & 15);
                    int n = wn * 64 + nt * 8;
                    ldmatrix_x2t(bf[nt], smem_u32(&Bs[row][n]));
                }
#pragma unroll
                for (int am = 0; am < 2; am++)
#pragma unroll
                    for (int nt = 0; nt < 8; nt++)
                        mma16816(acc[am][nt], af[am], bf[nt]);
            }
            __syncthreads();
        }
    }

    // epilogue: d0,d1 -> row r, cols c,c+1 ; d2,d3 -> row r+8
#pragma unroll
    for (int am = 0; am < 2; am++) {
        int r = v0 + wm * 32 + am * 16 + (lane >> 2);
#pragma unroll
        for (int nt = 0; nt < 8; nt++) {
            int col = wn * 64 + nt * 8 + (lane & 3) * 2;
            float2 bv = *(const float2*)&bias[col];
            if (r < V) {
                float2 o = make_float2(acc[am][nt][0] + bv.x, acc[am][nt][1] + bv.y);
                *(float2*)&out[((size_t)b * V + r) * FOUT + col] = o;
            }
            if (r + 8 < V) {
                float2 o = make_float2(acc[am][nt][2] + bv.x, acc[am][nt][3] + bv.y);
                *(float2*)&out[((size_t)b * V + r + 8) * FOUT + col] = o;
            }
        }
    }
}

// ---------------- launcher -------------------------------------------------
extern "C" void kernel_launch(void* const* d_in, const int* in_sizes, int n_in,
                              void* d_out, int out_size) {
    const int*   rows   = (const int*)d_in[0];
    const int*   cols   = (const int*)d_in[1];
    const float* vals   = (const float*)d_in[2];
    const float* inputs = (const float*)d_in[3];
    const float* weight = (const float*)d_in[4];
    const float* bias   = (const float*)d_in[5];
    float*       out    = (float*)d_out;

    zero_kernel<<<(V + 255) / 256, 256>>>();
    hist_kernel<<<(NNZ + 255) / 256, 256>>>(rows);
    scan_kernel<<<1, 1024>>>();
    scatter_kernel<<<(NNZ + 255) / 256, 256>>>(rows, cols, vals);
    transpose_kernel<<<(NB * V * 32 + 255) / 256, 256>>>(inputs);
    wconv_kernel<<<(KCH * FIN * FOUT + 255) / 256, 256>>>(weight);

    for (int k = 1; k < KCH; k++) {
        int kprev = (k >= 2) ? k - 2 : 0;
        int cheb  = (k >= 2) ? 1 : 0;
        spmm_kernel<<<(V + SPMM_RPB - 1) / SPMM_RPB, 128>>>(k, k - 1, kprev, cheb);
    }

    dim3 ggrid((V + 127) / 128, NB);
    gemm_kernel<<<ggrid, 256>>>(bias, out);
}

// round 8
// speedup vs baseline: 3.3372x; 1.1316x over previous
#include <cuda_runtime.h>
#include <cuda_fp16.h>

#define V 50000
#define NNZ 1600000
#define NB 4
#define FIN 128
#define FOUT 128
#define KCH 5
#define SPMM_RPB 2      // rows per block in spmm
#define NCHUNK 20       // gemm K chunks (5 k * 4 ch)

// ---------------- scratch (static device globals; no allocation allowed) ----
// Unified fp16 basis storage, plane-major: [k][b][v][128 fin]
__device__ __half g_Xh[KCH][NB][(size_t)V * 128];
__device__ __half g_Wh[KCH * FIN * FOUT];      // [k][fin][fo] fp16 weights
__device__ unsigned long long g_edge[NNZ];     // packed (val<<32 | col)
__device__ int    g_count[V];
__device__ int    g_cursor[V];
__device__ int    g_rowptr[V + 1];

// ---------------- CSR build ------------------------------------------------
__global__ void zero_kernel() {
    int i = blockIdx.x * blockDim.x + threadIdx.x;
    if (i < V) { g_count[i] = 0; g_cursor[i] = 0; }
}

__global__ void hist_kernel(const int* __restrict__ rows) {
    int i = blockIdx.x * blockDim.x + threadIdx.x;
    if (i < NNZ) atomicAdd(&g_count[rows[i]], 1);
}

// single-block exclusive scan over g_count -> g_rowptr
__global__ void scan_kernel() {
    __shared__ int warp_sums[32];
    __shared__ int s_carry;
    int tid = threadIdx.x, lane = tid & 31, wid = tid >> 5;
    if (tid == 0) s_carry = 0;
    __syncthreads();
    const int ntiles = (V + 1023) / 1024;
    for (int t = 0; t < ntiles; t++) {
        int carry = s_carry;
        int i = t * 1024 + tid;
        int v = (i < V) ? g_count[i] : 0;
        int x = v;
#pragma unroll
        for (int o = 1; o < 32; o <<= 1) {
            int n = __shfl_up_sync(0xFFFFFFFFu, x, o);
            if (lane >= o) x += n;
        }
        if (lane == 31) warp_sums[wid] = x;
        __syncthreads();
        if (wid == 0) {
            int s = warp_sums[lane];
#pragma unroll
            for (int o = 1; o < 32; o <<= 1) {
                int n = __shfl_up_sync(0xFFFFFFFFu, s, o);
                if (lane >= o) s += n;
            }
            warp_sums[lane] = s;
        }
        __syncthreads();
        int excl = carry + (x - v) + (wid > 0 ? warp_sums[wid - 1] : 0);
        if (i < V) g_rowptr[i] = excl;
        __syncthreads();
        if (tid == 0) s_carry = carry + warp_sums[31];
        __syncthreads();
    }
    if (threadIdx.x == 0) g_rowptr[V] = s_carry;
}

__global__ void scatter_kernel(const int* __restrict__ rows,
                               const int* __restrict__ cols,
                               const float* __restrict__ vals) {
    int i = blockIdx.x * blockDim.x + threadIdx.x;
    if (i < NNZ) {
        int r = rows[i];
        int p = g_rowptr[r] + atomicAdd(&g_cursor[r], 1);
        unsigned long long packed =
            ((unsigned long long)__float_as_uint(vals[i]) << 32) | (unsigned)cols[i];
        g_edge[p] = packed;
    }
}

// ---- pack float4 -> 2x half2 (as uint2) -----------------------------------
__device__ __forceinline__ uint2 pack_h4(float4 a) {
    __half2 h0 = __floats2half2_rn(a.x, a.y);
    __half2 h1 = __floats2half2_rn(a.z, a.w);
    uint2 r;
    r.x = *reinterpret_cast<unsigned*>(&h0);
    r.y = *reinterpret_cast<unsigned*>(&h1);
    return r;
}
__device__ __forceinline__ float2 h2f(unsigned u) {
    return __half22float2(*reinterpret_cast<__half2*>(&u));
}

// ---------------- transpose: inputs[b][v][f] fp32 -> plane (0,b) fp16 -------
__global__ void transpose_kernel(const float* __restrict__ inp) {
    int i = blockIdx.x * blockDim.x + threadIdx.x;
    if (i < NB * V * 32) {
        int q = i & 31, v = (i >> 5) % V, b = i / (V * 32);
        float4 o = *(const float4*)&inp[((size_t)b * V + v) * FIN + q * 4];
        ((uint2*)g_Xh[0][b])[(size_t)v * 32 + q] = pack_h4(o);
    }
}

// ---------------- weight fp16 conversion: g_Wh[k][fin][fo] ------------------
__global__ void wconv_kernel(const float* __restrict__ Wt) {
    int i = blockIdx.x * blockDim.x + threadIdx.x;
    if (i < KCH * FIN * FOUT) {
        int k = i / (FIN * FOUT), fin = (i / FOUT) % FIN, fo = i % FOUT;
        g_Wh[i] = __float2half(Wt[(size_t)(fin * KCH + k) * FOUT + fo]);
    }
}

// ---------------- SpMM: y = L*x  (or y = 2*L*x - xprev) ---------------------
// Plane-major fp16: warp w = batch plane; thread owns 4 fin cols (uint2).
// Edge metadata staged once per block in smem (was 4x redundant per warp).
__global__ void __launch_bounds__(128) spmm_kernel(int kout, int kin, int kprev, int cheb) {
    __shared__ int   sc[128];
    __shared__ float sv[128];
    int t = threadIdx.x;
    int b = t >> 5, q = t & 31;
    const uint2* __restrict__ x  = (const uint2*)g_Xh[kin][b];
    const uint2* __restrict__ xp = (const uint2*)g_Xh[kprev][b];
    uint2*       __restrict__ y  = (uint2*)g_Xh[kout][b];
    int r0 = blockIdx.x * SPMM_RPB;
    int r1 = min(r0 + SPMM_RPB, V);
    for (int r = r0; r < r1; r++) {
        int s = g_rowptr[r], e = g_rowptr[r + 1];
        float4 acc = make_float4(0.f, 0.f, 0.f, 0.f);
        for (int base = s; base < e; base += 128) {
            int n = min(128, e - base);
            __syncthreads();
            if (t < n) {
                unsigned long long p = __ldcs(&g_edge[base + t]);
                sc[t] = (int)(unsigned)p;
                sv[t] = __uint_as_float((unsigned)(p >> 32));
            }
            __syncthreads();
            int i = 0;
            for (; i + 4 <= n; i += 4) {
                int   c0 = sc[i],     c1 = sc[i + 1];
                int   c2 = sc[i + 2], c3 = sc[i + 3];
                float w0 = sv[i],     w1 = sv[i + 1];
                float w2 = sv[i + 2], w3 = sv[i + 3];
                uint2 h0 = __ldg(&x[(size_t)c0 * 32 + q]);
                uint2 h1 = __ldg(&x[(size_t)c1 * 32 + q]);
                uint2 h2 = __ldg(&x[(size_t)c2 * 32 + q]);
                uint2 h3 = __ldg(&x[(size_t)c3 * 32 + q]);
                float2 a0 = h2f(h0.x), b0 = h2f(h0.y);
                float2 a1 = h2f(h1.x), b1 = h2f(h1.y);
                float2 a2 = h2f(h2.x), b2 = h2f(h2.y);
                float2 a3 = h2f(h3.x), b3 = h2f(h3.y);
                acc.x += w0 * a0.x + w1 * a1.x + w2 * a2.x + w3 * a3.x;
                acc.y += w0 * a0.y + w1 * a1.y + w2 * a2.y + w3 * a3.y;
                acc.z += w0 * b0.x + w1 * b1.x + w2 * b2.x + w3 * b3.x;
                acc.w += w0 * b0.y + w1 * b1.y + w2 * b2.y + w3 * b3.y;
            }
            for (; i < n; i++) {
                int   c = sc[i];
                float w = sv[i];
                uint2 h = __ldg(&x[(size_t)c * 32 + q]);
                float2 a = h2f(h.x), bb = h2f(h.y);
                acc.x += w * a.x;  acc.y += w * a.y;
                acc.z += w * bb.x; acc.w += w * bb.y;
            }
        }
        size_t oi = (size_t)r * 32 + q;
        if (cheb) {
            uint2 ph = __ldcs(&xp[oi]);
            float2 p0 = h2f(ph.x), p1 = h2f(ph.y);
            acc.x = 2.f * acc.x - p0.x; acc.y = 2.f * acc.y - p0.y;
            acc.z = 2.f * acc.z - p1.x; acc.w = 2.f * acc.w - p1.y;
        }
        __stcs(&y[oi], pack_h4(acc));
    }
}

// ---------------- mma / cp.async helpers -----------------------------------
__device__ __forceinline__ unsigned smem_u32(const void* p) {
    return (unsigned)__cvta_generic_to_shared(p);
}
__device__ __forceinline__ void cp_async16(unsigned dst, const void* src) {
    asm volatile("cp.async.cg.shared.global [%0], [%1], 16;" :: "r"(dst), "l"(src));
}
__device__ __forceinline__ void cp_commit() {
    asm volatile("cp.async.commit_group;");
}
__device__ __forceinline__ void ldmatrix_x4(unsigned* r, unsigned a) {
    asm volatile("ldmatrix.sync.aligned.m8n8.x4.shared.b16 {%0,%1,%2,%3}, [%4];"
                 : "=r"(r[0]), "=r"(r[1]), "=r"(r[2]), "=r"(r[3]) : "r"(a));
}
__device__ __forceinline__ void ldmatrix_x2t(unsigned* r, unsigned a) {
    asm volatile("ldmatrix.sync.aligned.m8n8.x2.trans.shared.b16 {%0,%1}, [%2];"
                 : "=r"(r[0]), "=r"(r[1]) : "r"(a));
}
__device__ __forceinline__ void mma16816(float* d, const unsigned* a, const unsigned* b) {
    asm volatile("mma.sync.aligned.m16n8k16.row.col.f32.f16.f16.f32 "
                 "{%0,%1,%2,%3},{%4,%5,%6,%7},{%8,%9},{%0,%1,%2,%3};"
                 : "+f"(d[0]), "+f"(d[1]), "+f"(d[2]), "+f"(d[3])
                 : "r"(a[0]), "r"(a[1]), "r"(a[2]), "r"(a[3]),
                   "r"(b[0]), "r"(b[1]));
}

// ---------------- GEMM (tensor cores, double-buffered cp.async) -------------
// out[b*V+v][fo] = sum_{k,fin} Xh[k][b][v][fin] * Wh[k][fin][fo] + bias
// Block 128x128, 8 warps (4m x 2n) each 32x64, K=640 in 20 chunks of 32.
__global__ void __launch_bounds__(256) gemm_kernel(const float* __restrict__ bias,
                                                   float* __restrict__ out) {
    __shared__ __half As[2][128][40];
    __shared__ __half Bs[2][32][136];
    int t = threadIdx.x, lane = t & 31, wid = t >> 5;
    int wm = wid >> 1, wn = wid & 1;
    int v0 = blockIdx.x * 128;
    int b  = blockIdx.y;

    float acc[2][8][4];
#pragma unroll
    for (int am = 0; am < 2; am++)
#pragma unroll
        for (int nt = 0; nt < 8; nt++)
#pragma unroll
            for (int q = 0; q < 4; q++) acc[am][nt][q] = 0.f;

    // A loader coords (2 x uint4 per thread), B loader coords
    int arow0 = t >> 2,          aseg0 = t & 3;
    int arow1 = (t + 256) >> 2,  aseg1 = (t + 256) & 3;
    int brow0 = t >> 4,          bseg0 = t & 15;
    int brow1 = (t + 256) >> 4,  bseg1 = (t + 256) & 15;
    int av0 = min(v0 + arow0, V - 1);
    int av1 = min(v0 + arow1, V - 1);

#define LOAD_TILES(idx, buf)                                                        \
    {                                                                               \
        int kc_ = (idx) >> 2, ch_ = (idx) & 3;                                      \
        const __half* Ap_ = g_Xh[kc_][b];                                           \
        const __half* Bp_ = g_Wh + ((size_t)kc_ * FIN + ch_ * 32) * FOUT;           \
        cp_async16(smem_u32(&As[buf][arow0][aseg0 * 8]),                            \
                   Ap_ + (size_t)av0 * 128 + ch_ * 32 + aseg0 * 8);                 \
        cp_async16(smem_u32(&As[buf][arow1][aseg1 * 8]),                            \
                   Ap_ + (size_t)av1 * 128 + ch_ * 32 + aseg1 * 8);                 \
        cp_async16(smem_u32(&Bs[buf][brow0][bseg0 * 8]), Bp_ + brow0 * FOUT + bseg0 * 8); \
        cp_async16(smem_u32(&Bs[buf][brow1][bseg1 * 8]), Bp_ + brow1 * FOUT + bseg1 * 8); \
        cp_commit();                                                                \
    }

    LOAD_TILES(0, 0);

    for (int idx = 0; idx < NCHUNK; idx++) {
        int buf = idx & 1;
        if (idx + 1 < NCHUNK) {
            LOAD_TILES(idx + 1, buf ^ 1);
            asm volatile("cp.async.wait_group 1;");
        } else {
            asm volatile("cp.async.wait_group 0;");
        }
        __syncthreads();
#pragma unroll
        for (int ks = 0; ks < 32; ks += 16) {
            unsigned af[2][4], bf[8][2];
#pragma unroll
            for (int am = 0; am < 2; am++) {
                int m = wm * 32 + am * 16 + (lane & 15);
                int col = ks + (lane >> 4) * 8;
                ldmatrix_x4(af[am], smem_u32(&As[buf][m][col]));
            }
#pragma unroll
            for (int nt = 0; nt < 8; nt++) {
                int row = ks + (lane & 15);
                int n = wn * 64 + nt * 8;
                ldmatrix_x2t(bf[nt], smem_u32(&Bs[buf][row][n]));
            }
#pragma unroll
            for (int am = 0; am < 2; am++)
#pragma unroll
                for (int nt = 0; nt < 8; nt++)
                    mma16816(acc[am][nt], af[am], bf[nt]);
        }
        __syncthreads();
    }
#undef LOAD_TILES

    // epilogue: d0,d1 -> row r, cols c,c+1 ; d2,d3 -> row r+8
#pragma unroll
    for (int am = 0; am < 2; am++) {
        int r = v0 + wm * 32 + am * 16 + (lane >> 2);
#pragma unroll
        for (int nt = 0; nt < 8; nt++) {
            int col = wn * 64 + nt * 8 + (lane & 3) * 2;
            float2 bv = *(const float2*)&bias[col];
            if (r < V) {
                float2 o = make_float2(acc[am][nt][0] + bv.x, acc[am][nt][1] + bv.y);
                *(float2*)&out[((size_t)b * V + r) * FOUT + col] = o;
            }
            if (r + 8 < V) {
                float2 o = make_float2(acc[am][nt][2] + bv.x, acc[am][nt][3] + bv.y);
                *(float2*)&out[((size_t)b * V + r + 8) * FOUT + col] = o;
            }
        }
    }
}

// ---------------- launcher -------------------------------------------------
extern "C" void kernel_launch(void* const* d_in, const int* in_sizes, int n_in,
                              void* d_out, int out_size) {
    const int*   rows   = (const int*)d_in[0];
    const int*   cols   = (const int*)d_in[1];
    const float* vals   = (const float*)d_in[2];
    const float* inputs = (const float*)d_in[3];
    const float* weight = (const float*)d_in[4];
    const float* bias   = (const float*)d_in[5];
    float*       out    = (float*)d_out;

    zero_kernel<<<(V + 255) / 256, 256>>>();
    hist_kernel<<<(NNZ + 255) / 256, 256>>>(rows);
    scan_kernel<<<1, 1024>>>();
    scatter_kernel<<<(NNZ + 255) / 256, 256>>>(rows, cols, vals);
    transpose_kernel<<<(NB * V * 32 + 255) / 256, 256>>>(inputs);
    wconv_kernel<<<(KCH * FIN * FOUT + 255) / 256, 256>>>(weight);

    for (int k = 1; k < KCH; k++) {
        int kprev = (k >= 2) ? k - 2 : 0;
        int cheb  = (k >= 2) ? 1 : 0;
        spmm_kernel<<<(V + SPMM_RPB - 1) / SPMM_RPB, 128>>>(k, k - 1, kprev, cheb);
    }

    dim3 ggrid((V + 127) / 128, NB);
    gemm_kernel<<<ggrid, 256>>>(bias, out);
}